// round 11
// baseline (speedup 1.0000x reference)
#include <cuda_runtime.h>

#define CIN   64
#define PW    38            // padded width (32 + 2*3)
#define NPIX  1024          // 32*32
#define NPAD  (PW*PW)       // 1444

#define PLANES_BYTES (4*NPAD*16)                     // ktA,ktB,vtA,vtB = 92416
#define SMEM_BYTES   (PLANES_BYTES + 1536*4 + 224)   // + wt + rels = 98784

typedef unsigned long long ull;

__device__ __forceinline__ ull ffma2(ull a, ull b, ull c) {
    ull d;
    asm("fma.rn.f32x2 %0, %1, %2, %3;" : "=l"(d) : "l"(a), "l"(b), "l"(c));
    return d;
}
__device__ __forceinline__ ull add2(ull a, ull b) {
    ull d;
    asm("add.rn.f32x2 %0, %1, %2;" : "=l"(d) : "l"(a), "l"(b));
    return d;
}
__device__ __forceinline__ ull pk2(float a, float b) {
    ull r;
    asm("mov.b64 %0, {%1, %2};" : "=l"(r) : "f"(a), "f"(b));
    return r;
}
__device__ __forceinline__ float2 upk2(ull v) {
    float2 t;
    asm("mov.b64 {%0, %1}, %2;" : "=f"(t.x), "=f"(t.y) : "l"(v));
    return t;
}
__device__ __forceinline__ float ex2(float s) {
    float r;
    asm("ex2.approx.ftz.f32 %0, %1;" : "=f"(r) : "f"(s));
    return r;
}

struct KV { ulonglong2 ka, kb, va, vb; };

__device__ __forceinline__ KV ld4(
    const ulonglong2* __restrict__ ktA, const ulonglong2* __restrict__ ktB,
    const ulonglong2* __restrict__ vtA, const ulonglong2* __restrict__ vtB,
    int off)
{
    KV r;
    r.ka = ktA[off]; r.kb = ktB[off];
    r.va = vtA[off]; r.vb = vtB[off];
    return r;
}

// Compute one bias seed: (q . rel_idx) packed as (bias, 0).
__device__ __forceinline__ ull mk_seed(const ull (&Qo)[4],
                                       const ulonglong2* __restrict__ relp,
                                       int ridx)
{
    ulonglong2 r01 = relp[ridx*2], r23 = relp[ridx*2 + 1];
    ull cA = ffma2(Qo[0], r01.x, ffma2(Qo[1], r01.y, 0ULL));
    ull cB = ffma2(Qo[2], r23.x, ffma2(Qo[3], r23.y, 0ULL));
    float2 df = upk2(add2(cA, cB));
    return pk2(df.x + df.y, 0.f);
}

// One tap: score (tree-split, bias in chain-A seed) -> exp2 -> V accumulate.
__device__ __forceinline__ void do_tap(
    const ull (&Qo)[4], ull seed, const KV& t,
    float& Zo, ull (&ao)[4])
{
    ull cA = ffma2(Qo[0], t.ka.x, ffma2(Qo[1], t.ka.y, seed));
    ull cB = ffma2(Qo[2], t.kb.x, ffma2(Qo[3], t.kb.y, 0ULL));
    float2 sf = upk2(add2(cA, cB));
    float e = ex2(sf.x + sf.y);        // max-free softmax, log2 domain
    Zo += e;
    ull e2 = pk2(e, e);
    ao[0] = ffma2(e2, t.va.x, ao[0]);
    ao[1] = ffma2(e2, t.va.y, ao[1]);
    ao[2] = ffma2(e2, t.vb.x, ao[2]);
    ao[3] = ffma2(e2, t.vb.y, ao[3]);
}

// Phase 2 with explicit one-position software pipeline: the 4 LDS.128 for tap
// position n+1 issue BEFORE the ~40-instruction compute of position n, hiding
// the 29-cycle LDS latency that ptxas's tight register budget can't schedule
// around on its own. Seeds computed just-in-time (4 live).
// ISH: pr outer (bias by tap row). ISW: j outer (bias by tap col).
template<bool ISH>
__device__ __forceinline__ void phase2_run(
    const ulonglong2* __restrict__ ktA, const ulonglong2* __restrict__ ktB,
    const ulonglong2* __restrict__ vtA, const ulonglong2* __restrict__ vtB,
    const ulonglong2* __restrict__ relp,
    const ull (&Q)[4][4], float (&Z)[4], ull (&aa)[4][4], int h0, int w)
{
    const int base = h0*PW + w;
    KV cur = ld4(ktA, ktB, vtA, vtB, base);   // first position (0,0)

    if (ISH) {
        #pragma unroll
        for (int pr = 0; pr < 10; pr++) {
            ull seed[4];
            #pragma unroll
            for (int o = 0; o < 4; o++) {
                const int i = pr - o;
                if (i >= 0 && i < 7) seed[o] = mk_seed(Q[o], relp, i);
            }
            #pragma unroll
            for (int j = 0; j < 7; j++) {
                // prefetch next position (row-major walk)
                KV nxt;
                if (!(pr == 9 && j == 6)) {
                    const int noff = (j < 6) ? (pr*PW + base + j + 1)
                                             : ((pr + 1)*PW + base);
                    nxt = ld4(ktA, ktB, vtA, vtB, noff);
                }
                #pragma unroll
                for (int o = 0; o < 4; o++) {
                    const int i = pr - o;
                    if (i >= 0 && i < 7) do_tap(Q[o], seed[o], cur, Z[o], aa[o]);
                }
                cur = nxt;
            }
        }
    } else {
        #pragma unroll
        for (int j = 0; j < 7; j++) {
            ull seed[4];
            #pragma unroll
            for (int o = 0; o < 4; o++) seed[o] = mk_seed(Q[o], relp, j);
            #pragma unroll
            for (int pr = 0; pr < 10; pr++) {
                // prefetch next position (column-major walk)
                KV nxt;
                if (!(j == 6 && pr == 9)) {
                    const int noff = (pr < 9) ? ((pr + 1)*PW + base + j)
                                              : (base + j + 1);
                    nxt = ld4(ktA, ktB, vtA, vtB, noff);
                }
                #pragma unroll
                for (int o = 0; o < 4; o++) {
                    const int i = pr - o;
                    if (i >= 0 && i < 7) do_tap(Q[o], seed[o], cur, Z[o], aa[o]);
                }
                cur = nxt;
            }
        }
    }
}

// One CTA per (batch b, group g). 256 threads, 2 CTAs/SM resident.
// Each thread owns a column of 4 output rows.
// Phase 1: project q/k/v (f32x2 FMA); q weights pre-scaled by log2e at staging.
// Phase 2: R=4 row-blocked 7x7 local attention + adaptive ring mask.
__global__ __launch_bounds__(256, 2)
void attn_conv_fused(const float* __restrict__ x,
                     const float* __restrict__ wq,
                     const float* __restrict__ wk,
                     const float* __restrict__ wv,
                     const float* __restrict__ relh,
                     const float* __restrict__ relw,
                     const float* __restrict__ cval,
                     float* __restrict__ out)
{
    extern __shared__ char smem[];
    ulonglong2* ktA = (ulonglong2*)smem;
    ulonglong2* ktB = ktA + NPAD;
    ulonglong2* vtA = ktB + NPAD;
    ulonglong2* vtB = vtA + NPAD;
    float* wt   = (float*)(smem + PLANES_BYTES);     // [64 ci][24]
    float* rels = wt + 1536;                         // [7][8]

    const int g   = blockIdx.x;        // 0..7
    const int b   = blockIdx.y;
    const int tid = threadIdx.x;
    const int wr  = tid >> 5;          // warp 0..7
    const int w   = tid & 31;          // column
    const int h0  = wr * 4;            // first of 4 owned rows
    const bool isH = (g < 4);
    const float cvg = cval[g];         // early load, used in epilogue

    // ---- stage weights (transposed ci-major); q rows pre-scaled by log2e ----
    const float L2E = 1.4426950408889634f;
    for (int idx = tid; idx < 1536; idx += 256) {
        int ci = idx / 24, c = idx % 24;
        float v;
        if (c < 8)       v = wq[(g*8 + c)        * 64 + ci] * L2E;
        else if (c < 16) v = wk[(g*8 + (c - 8))  * 64 + ci];
        else             v = wv[(g*8 + (c - 16)) * 64 + ci];
        wt[idx] = v;
    }
    if (tid < 56) {
        int i = tid >> 3, c = tid & 7;
        rels[tid] = isH ? relh[(g*8 + c)*7 + i]
                        : relw[((g - 4)*8 + c)*7 + i];
    }
    // ---- zero ONLY the halo border of the k/v planes (420 cells/plane) ----
    {
        ulonglong2 z; z.x = 0ULL; z.y = 0ULL;
        for (int idx = tid; idx < 420; idx += 256) {
            int row, col;
            if (idx < 114)      { row = idx / 38;              col = idx % 38; }
            else if (idx < 228) { int k2 = idx - 114; row = 35 + k2/38; col = k2%38; }
            else                { int k2 = idx - 228; row = 3 + k2/6;
                                  int c6 = k2 % 6;  col = (c6 < 3) ? c6 : 32 + c6; }
            int off = row*PW + col;
            ktA[off] = z; ktB[off] = z; vtA[off] = z; vtB[off] = z;
        }
    }
    __syncthreads();

    const ulonglong2* relp = (const ulonglong2*)rels;  // [7][2]

    // ---- Phase 1: projection for the 4 owned pixels (2 passes of 2 rows) ----
    ull Q[4][4];         // q (carries log2e via staged weights), 8 ch packed
    const float* xb = x + (size_t)b * CIN * NPIX;

    #pragma unroll
    for (int pass = 0; pass < 2; pass++) {
        const int r0 = h0 + 2*pass;
        ull acc[2][12];
        #pragma unroll
        for (int e = 0; e < 2; e++)
            #pragma unroll
            for (int p = 0; p < 12; p++) acc[e][p] = 0ULL;

        #pragma unroll 8
        for (int ci = 0; ci < 64; ci++) {
            float x0 = xb[ci*NPIX + r0*32 + w];
            float x1 = xb[ci*NPIX + (r0+1)*32 + w];
            ull xp0 = pk2(x0, x0);
            ull xp1 = pk2(x1, x1);
            const ulonglong2* wrow = (const ulonglong2*)(wt + ci*24);
            #pragma unroll
            for (int p = 0; p < 6; p++) {
                ulonglong2 wv2 = wrow[p];
                acc[0][2*p]   = ffma2(xp0, wv2.x, acc[0][2*p]);
                acc[0][2*p+1] = ffma2(xp0, wv2.y, acc[0][2*p+1]);
                acc[1][2*p]   = ffma2(xp1, wv2.x, acc[1][2*p]);
                acc[1][2*p+1] = ffma2(xp1, wv2.y, acc[1][2*p+1]);
            }
        }
        #pragma unroll
        for (int e = 0; e < 2; e++) {
            const int o = 2*pass + e;
            Q[o][0] = acc[e][0]; Q[o][1] = acc[e][1];
            Q[o][2] = acc[e][2]; Q[o][3] = acc[e][3];
            const int pi = (h0 + o + 3)*PW + (w + 3);
            ulonglong2 tkv;
            tkv.x = acc[e][4];  tkv.y = acc[e][5];  ktA[pi] = tkv;
            tkv.x = acc[e][6];  tkv.y = acc[e][7];  ktB[pi] = tkv;
            tkv.x = acc[e][8];  tkv.y = acc[e][9];  vtA[pi] = tkv;
            tkv.x = acc[e][10]; tkv.y = acc[e][11]; vtB[pi] = tkv;
        }
    }
    __syncthreads();

    // ---- Phase 2 ----
    float Z[4] = {0.f, 0.f, 0.f, 0.f};
    ull aa[4][4];
    #pragma unroll
    for (int o = 0; o < 4; o++)
        #pragma unroll
        for (int p = 0; p < 4; p++) aa[o][p] = 0ULL;

    if (isH) phase2_run<true >(ktA, ktB, vtA, vtB, relp, Q, Z, aa, h0, w);
    else     phase2_run<false>(ktA, ktB, vtA, vtB, relp, Q, Z, aa, h0, w);

    // ---- epilogue: adaptive ring mask + normalize + store ----
    float* outbase = out + ((size_t)b * 64 + g * 8) * NPIX;
    #pragma unroll
    for (int o = 0; o < 4; o++) {
        const int h   = h0 + o;
        const int pos = h*32 + w;
        int r  = min(h, 31 - h);
        int lo = (h <= 31 - h) ? r : r + 1;
        int hi = 31 - r;
        float omv  = fminf(fmaxf(((float)(r - 15) + cvg*16.0f)*(1.0f/3.0f) + 1.0f,
                                 0.0f), 1.0f);
        float mval = (w >= lo && w <= hi) ? omv : 1.0f;
        float sc   = __fdividef(mval, Z[o]);

        float2 o01 = upk2(aa[o][0]), o23 = upk2(aa[o][1]);
        float2 o45 = upk2(aa[o][2]), o67 = upk2(aa[o][3]);
        outbase[0*NPIX + pos] = o01.x * sc;
        outbase[1*NPIX + pos] = o01.y * sc;
        outbase[2*NPIX + pos] = o23.x * sc;
        outbase[3*NPIX + pos] = o23.y * sc;
        outbase[4*NPIX + pos] = o45.x * sc;
        outbase[5*NPIX + pos] = o45.y * sc;
        outbase[6*NPIX + pos] = o67.x * sc;
        outbase[7*NPIX + pos] = o67.y * sc;
    }
}

extern "C" void kernel_launch(void* const* d_in, const int* in_sizes, int n_in,
                              void* d_out, int out_size)
{
    const float* x    = (const float*)d_in[0];
    const float* wq   = (const float*)d_in[1];
    const float* wk   = (const float*)d_in[2];
    const float* wv   = (const float*)d_in[3];
    const float* relh = (const float*)d_in[4];
    const float* relw = (const float*)d_in[5];
    const float* cv   = (const float*)d_in[6];
    float* out = (float*)d_out;

    cudaFuncSetAttribute(attn_conv_fused,
                         cudaFuncAttributeMaxDynamicSharedMemorySize, SMEM_BYTES);
    attn_conv_fused<<<dim3(8, 32), 256, SMEM_BYTES>>>(x, wq, wk, wv, relh, relw, cv, out);
}